// round 11
// baseline (speedup 1.0000x reference)
#include <cuda_runtime.h>
#include <math.h>

#define NF 128
#define F 8
#define CAP 60            // slots per node record (deg ~ Poisson(16); P(>=61) ~ 1e-14)
#define N_MAX 131072
#define B_MAX 64
#define NN_TILE 2048

// One 128B record per node: counter + src-id slots share the L2 line.
struct __align__(128) Row {
    int cnt;
    int pad;
    unsigned short s[CAP];     // 8B-aligned, 120 bytes
};

// scratch (module-static, allowed; BSS zero-initialized at load)
__device__ Row            g_rows[N_MAX];            // 16 MB
__device__ float          g_p[(size_t)N_MAX * F];   // x @ W1a
__device__ float          g_q[(size_t)N_MAX * F];   // h @ W2a
__device__ float          g_y[B_MAX * 4];           // [graph][half][class]
__device__ unsigned int   g_done;

__device__ __forceinline__ float lrelu(float v) {
    return v >= 0.f ? v : 0.01f * v;
}

// ---- packed f32x2 helpers (sm_103a; ptxas never emits FFMA2 from C++) ----
__device__ __forceinline__ unsigned long long ffma2(
    unsigned long long a, unsigned long long b, unsigned long long c) {
    unsigned long long d;
    asm("fma.rn.f32x2 %0, %1, %2, %3;" : "=l"(d) : "l"(a), "l"(b), "l"(c));
    return d;
}
__device__ __forceinline__ unsigned long long bcast2(float x) {
    unsigned long long r;
    asm("mov.b64 %0, {%1, %1};" : "=l"(r) : "f"(x));
    return r;
}
__device__ __forceinline__ float2 unpack2(unsigned long long v) {
    float2 f;
    asm("mov.b64 {%0, %1}, %2;" : "=f"(f.x), "=f"(f.y) : "l"(v));
    return f;
}

// ---------------------------------------------------------------------------
// scatter: row-record CSR build. Own kernel -> own (low) register budget.
// In-block dtype detect: int64 -> first 256 high 32-bit words all zero.
// magic = floor(2^45/NN)+1: g = (d*magic)>>45 (exact for NN<=16384, d<2^31).
// ---------------------------------------------------------------------------
__global__ void __launch_bounds__(256) scatter_kernel(
    const void* __restrict__ ei, int E, int NN, unsigned long long magic)
{
    __shared__ unsigned int sdet[8];
    int tid = threadIdx.x;
    unsigned int v = ((const unsigned int*)ei)[2 * (tid & 255) + 1];
#pragma unroll
    for (int off = 16; off > 0; off >>= 1)
        v |= __shfl_xor_sync(0xffffffffu, v, off);
    if ((tid & 31) == 0) sdet[tid >> 5] = v;
    __syncthreads();
    unsigned int all = sdet[0] | sdet[1] | sdet[2] | sdet[3]
                     | sdet[4] | sdet[5] | sdet[6] | sdet[7];
    int is64 = (all == 0u);

    int e0 = blockIdx.x * 512 + tid * 2;
    if (e0 >= E) return;
    unsigned int s0, d0, s1, d1;
    bool has2 = (e0 + 1 < E);
    if (is64) {
        const long long* p = (const long long*)ei;
        ulonglong2 sv = *(const ulonglong2*)(p + e0);
        ulonglong2 dv = *(const ulonglong2*)(p + (size_t)E + e0);
        s0 = (unsigned int)sv.x; s1 = (unsigned int)sv.y;
        d0 = (unsigned int)dv.x; d1 = (unsigned int)dv.y;
    } else {
        const int* p = (const int*)ei;
        uint2 sv = *(const uint2*)(p + e0);
        uint2 dv = *(const uint2*)(p + (size_t)E + e0);
        s0 = sv.x; s1 = sv.y;
        d0 = dv.x; d1 = dv.y;
    }
    {
        unsigned int grp = (unsigned int)(((unsigned long long)d0 * magic) >> 45);
        unsigned int base = grp * (unsigned int)NN;
        int pos = atomicAdd(&g_rows[d0].cnt, 1);
        if (pos > CAP - 1) pos = CAP - 1;
        g_rows[d0].s[pos] = (unsigned short)(s0 - base);
    }
    if (has2) {
        unsigned int grp = (unsigned int)(((unsigned long long)d1 * magic) >> 45);
        unsigned int base = grp * (unsigned int)NN;
        int pos = atomicAdd(&g_rows[d1].cnt, 1);
        if (pos > CAP - 1) pos = CAP - 1;
        g_rows[d1].s[pos] = (unsigned short)(s1 - base);
    }
}

// ---------------------------------------------------------------------------
// proj: smem-tiled x @ W1a (128->8). Own kernel -> regs don't tax scatter.
// Tile staging is fully coalesced (1 line per warp-instr); stride-33 rows are
// conflict-free for both the write and the per-node read phase.
// ---------------------------------------------------------------------------
__global__ void __launch_bounds__(256) proj_kernel(
    const float* __restrict__ x, const float* __restrict__ W1a, int N)
{
    __shared__ __align__(16) float sw[NF * F];   // [k][o], 4 KB
    __shared__ float sx[256 * 33];               // 256 nodes x 32 k, pad 1
    int tid = threadIdx.x;
    for (int i = tid; i < NF * F; i += 256) sw[i] = W1a[i];

    const int n0 = blockIdx.x * 256;
    const ulonglong2* swv = (const ulonglong2*)sw;   // 2 per k (8 floats)
    unsigned long long A0 = 0ull, A1 = 0ull, A2 = 0ull, A3 = 0ull;

    for (int kc = 0; kc < 4; kc++) {
        __syncthreads();
        // 32 iterations x 256 threads = 8192 = full 256x32 tile.
#pragma unroll 16
        for (int it = 0; it < 32; it++) {
            int j = it * 256 + tid;
            int r = j >> 5, c = j & 31;
            int row = n0 + r; if (row >= N) row = N - 1;
            sx[r * 33 + c] = __ldg(&x[(size_t)row * NF + kc * 32 + c]);
        }
        __syncthreads();
        const float* myrow = &sx[tid * 33];      // banks (tid+c)%32: cf
#pragma unroll
        for (int c = 0; c < 32; c++) {
            float xk = myrow[c];
            int k = kc * 32 + c;
            unsigned long long xx = bcast2(xk);
            ulonglong2 w0 = swv[2 * k];
            ulonglong2 w1 = swv[2 * k + 1];
            A0 = ffma2(xx, w0.x, A0);
            A1 = ffma2(xx, w0.y, A1);
            A2 = ffma2(xx, w1.x, A2);
            A3 = ffma2(xx, w1.y, A3);
        }
    }
    int n = n0 + tid;
    if (n < N) {
        float2 r0 = unpack2(A0), r1 = unpack2(A1);
        float2 r2 = unpack2(A2), r3 = unpack2(A3);
        float4* o4 = (float4*)(g_p + (size_t)n * F);
        o4[0] = make_float4(r0.x, r0.y, r1.x, r1.y);
        o4[1] = make_float4(r2.x, r2.y, r3.x, r3.y);
    }
}

// ---------------------------------------------------------------------------
// Shared-memory gather: acc += plane[idx] for 4 packed ushort ids (8B aligned)
// ---------------------------------------------------------------------------
#define GATHER4(P0, P1, ROWP, I, A0, A1)                                      \
    do {                                                                      \
        uint2 w = *(const uint2*)((ROWP) + (I));                              \
        unsigned r0 = w.x & 0xffffu, r1 = w.x >> 16;                          \
        unsigned r2 = w.y & 0xffffu, r3 = w.y >> 16;                          \
        float4 u0 = (P0)[r0], u1 = (P0)[r1], u2 = (P0)[r2], u3 = (P0)[r3];    \
        float4 v0 = (P1)[r0], v1 = (P1)[r1], v2 = (P1)[r2], v3 = (P1)[r3];    \
        (A0).x += (u0.x + u1.x) + (u2.x + u3.x);                              \
        (A0).y += (u0.y + u1.y) + (u2.y + u3.y);                              \
        (A0).z += (u0.z + u1.z) + (u2.z + u3.z);                              \
        (A0).w += (u0.w + u1.w) + (u2.w + u3.w);                              \
        (A1).x += (v0.x + v1.x) + (v2.x + v3.x);                              \
        (A1).y += (v0.y + v1.y) + (v2.y + v3.y);                              \
        (A1).z += (v0.z + v1.z) + (v2.z + v3.z);                              \
        (A1).w += (v0.w + v1.w) + (v2.w + v3.w);                              \
    } while (0)

#define GATHER_TAIL(P0, P1, ROWP, I, A0, A1)                                  \
    do {                                                                      \
        unsigned r = (ROWP)[I];                                               \
        float4 u = (P0)[r], v = (P1)[r];                                      \
        (A0).x += u.x; (A0).y += u.y; (A0).z += u.z; (A0).w += u.w;           \
        (A1).x += v.x; (A1).y += v.y; (A1).z += v.z; (A1).w += v.w;           \
    } while (0)

// ---------------------------------------------------------------------------
// layer1: 2 CTAs/graph; p tile in smem; gather via LDS; conv1 MLP; q -> g_q
// ---------------------------------------------------------------------------
__global__ void __launch_bounds__(1024) layer1_kernel(
    const float* __restrict__ b1a, const float* __restrict__ W1b,
    const float* __restrict__ b1b, const float* __restrict__ W2a, int NN)
{
    extern __shared__ float4 smp[];
    float4* sP0 = smp;
    float4* sP1 = smp + NN_TILE;
    __shared__ float sb1a[F], sb1b[F], sW1b[F * F], sW2a[F * F];

    const int tid = threadIdx.x;
    const int g = blockIdx.x >> 1;
    const int half = blockIdx.x & 1;

    if (tid < F) { sb1a[tid] = b1a[tid]; sb1b[tid] = b1b[tid]; }
    if (tid < F * F) { sW1b[tid] = W1b[tid]; sW2a[tid] = W2a[tid]; }

    const float4* src = (const float4*)(g_p + (size_t)g * NN * F);
    for (int i = tid; i < NN * 2; i += 1024) {
        float4 v = src[i];
        if (i & 1) sP1[i >> 1] = v; else sP0[i >> 1] = v;
    }
    __syncthreads();

    const int nh = (NN + 1) >> 1;
    const int local = half * nh + tid;
    if (tid >= nh || local >= NN) return;
    const int n = g * NN + local;

    float4 a0 = sP0[local], a1 = sP1[local];     // self term (eps = 0)
    int deg = g_rows[n].cnt; if (deg > CAP) deg = CAP;
    const unsigned short* row = g_rows[n].s;

    int i = 0;
    for (; i + 4 <= deg; i += 4) GATHER4(sP0, sP1, row, i, a0, a1);
    for (; i < deg; i++) GATHER_TAIL(sP0, sP1, row, i, a0, a1);

    float z[F];
    z[0] = lrelu(a0.x + sb1a[0]); z[1] = lrelu(a0.y + sb1a[1]);
    z[2] = lrelu(a0.z + sb1a[2]); z[3] = lrelu(a0.w + sb1a[3]);
    z[4] = lrelu(a1.x + sb1a[4]); z[5] = lrelu(a1.y + sb1a[5]);
    z[6] = lrelu(a1.z + sb1a[6]); z[7] = lrelu(a1.w + sb1a[7]);

    float h[F];
#pragma unroll
    for (int o = 0; o < F; o++) {
        float a = sb1b[o];
#pragma unroll
        for (int k = 0; k < F; k++) a += z[k] * sW1b[k * F + o];
        h[o] = lrelu(a);                  // conv1 out + inter-layer lrelu
    }
    float q[F];
#pragma unroll
    for (int o = 0; o < F; o++) {
        float a = 0.f;
#pragma unroll
        for (int k = 0; k < F; k++) a += h[k] * sW2a[k * F + o];
        q[o] = a;
    }
    float4* qo = (float4*)(g_q + (size_t)n * F);
    qo[0] = make_float4(q[0], q[1], q[2], q[3]);
    qo[1] = make_float4(q[4], q[5], q[6], q[7]);
}

// ---------------------------------------------------------------------------
// layer2 + head + finalize: 2 CTAs/graph; q tile in smem; FC1/FC2; last CTA
// does bf2 + log_softmax and resets g_done. Also zeroes row counters.
// ---------------------------------------------------------------------------
__global__ void __launch_bounds__(1024) layer2_kernel(
    const float* __restrict__ b2a, const float* __restrict__ W2b,
    const float* __restrict__ b2b, const float* __restrict__ Wf1,
    const float* __restrict__ bf1, const float* __restrict__ Wf2,
    const float* __restrict__ bf2, float* __restrict__ out, int NN, int B)
{
    extern __shared__ float4 smp[];
    float4* sP0 = smp;
    float4* sP1 = smp + NN_TILE;
    __shared__ float sb2a[F], sb2b[F], sW2b[F * F], sWf1[F];
    __shared__ float sred[64];
    __shared__ unsigned int s_t;

    const int tid = threadIdx.x;
    const int g = blockIdx.x >> 1;
    const int half = blockIdx.x & 1;

    if (tid < F) { sb2a[tid] = b2a[tid]; sb2b[tid] = b2b[tid]; sWf1[tid] = Wf1[tid]; }
    if (tid < F * F) sW2b[tid] = W2b[tid];

    const float4* src = (const float4*)(g_q + (size_t)g * NN * F);
    for (int i = tid; i < NN * 2; i += 1024) {
        float4 v = src[i];
        if (i & 1) sP1[i >> 1] = v; else sP0[i >> 1] = v;
    }
    __syncthreads();

    const int nh = (NN + 1) >> 1;
    const int local = half * nh + tid;
    const float bf1v = bf1[0];

    float c0 = 0.f, c1 = 0.f;
    if (tid < nh && local < NN) {
        const int n = g * NN + local;
        float4 a0 = sP0[local], a1 = sP1[local];
        int deg = g_rows[n].cnt;
        g_rows[n].cnt = 0;                 // restore invariant for next replay
        if (deg > CAP) deg = CAP;
        const unsigned short* row = g_rows[n].s;

        int i = 0;
        for (; i + 4 <= deg; i += 4) GATHER4(sP0, sP1, row, i, a0, a1);
        for (; i < deg; i++) GATHER_TAIL(sP0, sP1, row, i, a0, a1);

        float z[F];
        z[0] = lrelu(a0.x + sb2a[0]); z[1] = lrelu(a0.y + sb2a[1]);
        z[2] = lrelu(a0.z + sb2a[2]); z[3] = lrelu(a0.w + sb2a[3]);
        z[4] = lrelu(a1.x + sb2a[4]); z[5] = lrelu(a1.y + sb2a[5]);
        z[6] = lrelu(a1.z + sb2a[6]); z[7] = lrelu(a1.w + sb2a[7]);

        float fc1 = bf1v;
#pragma unroll
        for (int o = 0; o < F; o++) {
            float a = sb2b[o];
#pragma unroll
            for (int k = 0; k < F; k++) a += z[k] * sW2b[k * F + o];
            fc1 += lrelu(a) * sWf1[o];     // lrelu(h2) @ Wf1
        }
        float gv = lrelu(fc1);             // lrelu before FC2
        float2 wf = __ldg((const float2*)(Wf2 + (size_t)local * 2));
        c0 = gv * wf.x;
        c1 = gv * wf.y;
    }
#pragma unroll
    for (int off = 16; off > 0; off >>= 1) {
        c0 += __shfl_down_sync(0xffffffffu, c0, off);
        c1 += __shfl_down_sync(0xffffffffu, c1, off);
    }
    int wid = tid >> 5, lid = tid & 31;
    if (lid == 0) { sred[wid] = c0; sred[wid + 32] = c1; }
    __syncthreads();
    if (tid == 0) {
        float s0 = 0.f, s1 = 0.f;
        for (int w = 0; w < 32; w++) { s0 += sred[w]; s1 += sred[w + 32]; }
        g_y[g * 4 + half * 2 + 0] = s0;    // per-(graph,half): no atomics
        g_y[g * 4 + half * 2 + 1] = s1;
        __threadfence();                   // release g_y before done-count
        s_t = atomicAdd(&g_done, 1u);
    }
    __syncthreads();
    if (s_t == (unsigned int)(gridDim.x - 1)) {
        __threadfence();                   // acquire: all g_y stores visible
        if (tid < B) {
            float y0 = g_y[tid * 4 + 0] + g_y[tid * 4 + 2] + bf2[0];
            float y1 = g_y[tid * 4 + 1] + g_y[tid * 4 + 3] + bf2[1];
            float m = fmaxf(y0, y1);
            float l = logf(expf(y0 - m) + expf(y1 - m));
            out[tid * 2 + 0] = y0 - m - l;
            out[tid * 2 + 1] = y1 - m - l;
        }
        if (tid == 0) g_done = 0;          // reset for next replay
    }
}

// ---------------------------------------------------------------------------
extern "C" void kernel_launch(void* const* d_in, const int* in_sizes, int n_in,
                              void* d_out, int out_size) {
    const float* x   = (const float*)d_in[0];
    const void*  ei  = d_in[1];
    const float* W1a = (const float*)d_in[3];
    const float* b1a = (const float*)d_in[4];
    const float* W1b = (const float*)d_in[5];
    const float* b1b = (const float*)d_in[6];
    const float* W2a = (const float*)d_in[7];
    const float* b2a = (const float*)d_in[8];
    const float* W2b = (const float*)d_in[9];
    const float* b2b = (const float*)d_in[10];
    const float* Wf1 = (const float*)d_in[11];
    const float* bf1 = (const float*)d_in[12];
    const float* Wf2 = (const float*)d_in[13];
    const float* bf2 = (const float*)d_in[14];
    float* out = (float*)d_out;

    int N = in_sizes[0] / NF;          // 128000
    int E = in_sizes[1] / 2;           // 2048000
    int B = out_size / 2;              // 64
    int NN = N / B;                    // 2000
    if (N > N_MAX) N = N_MAX;

    unsigned long long magic = ((1ull << 45) / (unsigned long long)NN) + 1ull;

    scatter_kernel<<<(E + 511) / 512, 256>>>(ei, E, NN, magic);
    proj_kernel<<<(N + 255) / 256, 256>>>(x, W1a, N);

    size_t smem = (size_t)NN_TILE * 2 * sizeof(float4);   // 64 KB
    cudaFuncSetAttribute(layer1_kernel,
                         cudaFuncAttributeMaxDynamicSharedMemorySize, (int)smem);
    cudaFuncSetAttribute(layer2_kernel,
                         cudaFuncAttributeMaxDynamicSharedMemorySize, (int)smem);
    layer1_kernel<<<B * 2, 1024, smem>>>(b1a, W1b, b1b, W2a, NN);
    layer2_kernel<<<B * 2, 1024, smem>>>(b2a, W2b, b2b, Wf1, bf1, Wf2,
                                         bf2, out, NN, B);
}

// round 12
// speedup vs baseline: 1.7558x; 1.7558x over previous
#include <cuda_runtime.h>
#include <math.h>

#define NF 128
#define F 8
#define CAP 64            // padded CSR slots per node (deg ~ Poisson(16))
#define N_MAX 131072
#define B_MAX 64
#define NN_TILE 2048

// scratch (module-static, allowed; BSS zero-initialized at load)
__device__ unsigned short g_csr16[(size_t)N_MAX * CAP];  // 16 MB, local src ids
__device__ int            g_cnt[N_MAX];                  // re-zeroed by layer2
__device__ float          g_p[(size_t)N_MAX * F];        // x @ W1a
__device__ float          g_q[(size_t)N_MAX * F];        // h @ W2a
__device__ float          g_y[B_MAX * 4];                // [graph][half][class]
__device__ unsigned int   g_done;                        // reset by last CTA

__device__ __forceinline__ float lrelu(float v) {
    return v >= 0.f ? v : 0.01f * v;
}

// ---------------------------------------------------------------------------
// Fused proj (x@W1a, thread-per-node) + scatter (CSR build, 4 edges/thread).
// Scatter blocks self-detect the edge dtype: int64 -> first 256 high 32-bit
// words are all zero (node ids < 2^31); int32 -> those words are node ids.
// magic = floor(2^45/NN)+1: grp = (d*magic)>>45 exact for d < 2^34.
// ---------------------------------------------------------------------------
__global__ void __launch_bounds__(256) work_kernel(
    const float* __restrict__ x, const float* __restrict__ W1a,
    const void* __restrict__ ei, int N, int E, int NN,
    unsigned long long magic, int projB)
{
    if ((int)blockIdx.x < projB) {
        // ---------- proj (R6-proven: 33 regs, occ ~68%) ----------
        __shared__ float sw[NF * F];
        int tid = threadIdx.x;
        for (int i = tid; i < NF * F; i += 256) sw[i] = W1a[i];
        __syncthreads();

        int n = blockIdx.x * 256 + tid;
        if (n >= N) return;

        const float4* xg = (const float4*)x + (size_t)n * (NF / 4);
        float acc[F];
#pragma unroll
        for (int o = 0; o < F; o++) acc[o] = 0.f;
#pragma unroll 4
        for (int k4 = 0; k4 < NF / 4; k4++) {
            float4 xv = __ldg(xg + k4);
            int kb = k4 * 4;
#pragma unroll
            for (int kk = 0; kk < 4; kk++) {
                float xk = (kk == 0) ? xv.x : (kk == 1) ? xv.y
                          : (kk == 2) ? xv.z : xv.w;
                float4 w0 = *(const float4*)&sw[(kb + kk) * F];
                float4 w1 = *(const float4*)&sw[(kb + kk) * F + 4];
                acc[0] += xk * w0.x; acc[1] += xk * w0.y;
                acc[2] += xk * w0.z; acc[3] += xk * w0.w;
                acc[4] += xk * w1.x; acc[5] += xk * w1.y;
                acc[6] += xk * w1.z; acc[7] += xk * w1.w;
            }
        }
        float4* o4 = (float4*)(g_p + (size_t)n * F);
        o4[0] = make_float4(acc[0], acc[1], acc[2], acc[3]);
        o4[1] = make_float4(acc[4], acc[5], acc[6], acc[7]);
    } else {
        // ---------- scatter: 4 edges/thread, wide loads, magic div ----------
        __shared__ unsigned int sdet[8];
        int tid = threadIdx.x;
        unsigned int v = ((const unsigned int*)ei)[2 * tid + 1];  // E >= 256
#pragma unroll
        for (int off = 16; off > 0; off >>= 1)
            v |= __shfl_xor_sync(0xffffffffu, v, off);
        if ((tid & 31) == 0) sdet[tid >> 5] = v;
        __syncthreads();
        unsigned int all = sdet[0] | sdet[1] | sdet[2] | sdet[3]
                         | sdet[4] | sdet[5] | sdet[6] | sdet[7];
        int is64 = (all == 0u);

        int e0 = (blockIdx.x - projB) * 1024 + tid * 4;
        if (e0 >= E) return;

        unsigned int s[4], d[4];
        int cnt4 = (E - e0 >= 4) ? 4 : (E - e0);
        if (is64) {
            const long long* p = (const long long*)ei;
            if (cnt4 == 4) {
                ulonglong2 sa = *(const ulonglong2*)(p + e0);
                ulonglong2 sb = *(const ulonglong2*)(p + e0 + 2);
                ulonglong2 da = *(const ulonglong2*)(p + (size_t)E + e0);
                ulonglong2 db = *(const ulonglong2*)(p + (size_t)E + e0 + 2);
                s[0] = (unsigned int)sa.x; s[1] = (unsigned int)sa.y;
                s[2] = (unsigned int)sb.x; s[3] = (unsigned int)sb.y;
                d[0] = (unsigned int)da.x; d[1] = (unsigned int)da.y;
                d[2] = (unsigned int)db.x; d[3] = (unsigned int)db.y;
            } else {
                for (int j = 0; j < cnt4; j++) {
                    s[j] = (unsigned int)p[e0 + j];
                    d[j] = (unsigned int)p[(size_t)E + e0 + j];
                }
            }
        } else {
            const int* p = (const int*)ei;
            if (cnt4 == 4) {
                uint4 sa = *(const uint4*)(p + e0);
                uint4 da = *(const uint4*)(p + (size_t)E + e0);
                s[0] = sa.x; s[1] = sa.y; s[2] = sa.z; s[3] = sa.w;
                d[0] = da.x; d[1] = da.y; d[2] = da.z; d[3] = da.w;
            } else {
                for (int j = 0; j < cnt4; j++) {
                    s[j] = (unsigned int)p[e0 + j];
                    d[j] = (unsigned int)p[(size_t)E + e0 + j];
                }
            }
        }
        // issue all atomics back-to-back (independent -> 4 in flight)
        int pos[4];
#pragma unroll
        for (int j = 0; j < 4; j++)
            if (j < cnt4) pos[j] = atomicAdd(&g_cnt[d[j]], 1);
#pragma unroll
        for (int j = 0; j < 4; j++) {
            if (j < cnt4) {
                unsigned int grp =
                    (unsigned int)(((unsigned long long)d[j] * magic) >> 45);
                unsigned int base = grp * (unsigned int)NN;
                int p4 = pos[j]; if (p4 > CAP - 1) p4 = CAP - 1;
                g_csr16[(size_t)d[j] * CAP + p4] =
                    (unsigned short)(s[j] - base);
            }
        }
    }
}

// ---------------------------------------------------------------------------
// Shared-memory gather: acc += plane[idx] for 8 packed ushort ids
// ---------------------------------------------------------------------------
#define GATHER8(P0, P1, ROWP, I, A0, A1)                                      \
    do {                                                                      \
        uint4 w = *(const uint4*)((ROWP) + (I));                              \
        unsigned r0 = w.x & 0xffffu, r1 = w.x >> 16;                          \
        unsigned r2 = w.y & 0xffffu, r3 = w.y >> 16;                          \
        unsigned r4 = w.z & 0xffffu, r5 = w.z >> 16;                          \
        unsigned r6 = w.w & 0xffffu, r7 = w.w >> 16;                          \
        float4 u0 = (P0)[r0], u1 = (P0)[r1], u2 = (P0)[r2], u3 = (P0)[r3];    \
        float4 u4 = (P0)[r4], u5 = (P0)[r5], u6 = (P0)[r6], u7 = (P0)[r7];    \
        float4 v0 = (P1)[r0], v1 = (P1)[r1], v2 = (P1)[r2], v3 = (P1)[r3];    \
        float4 v4 = (P1)[r4], v5 = (P1)[r5], v6 = (P1)[r6], v7 = (P1)[r7];    \
        (A0).x += ((u0.x + u1.x) + (u2.x + u3.x)) + ((u4.x + u5.x) + (u6.x + u7.x)); \
        (A0).y += ((u0.y + u1.y) + (u2.y + u3.y)) + ((u4.y + u5.y) + (u6.y + u7.y)); \
        (A0).z += ((u0.z + u1.z) + (u2.z + u3.z)) + ((u4.z + u5.z) + (u6.z + u7.z)); \
        (A0).w += ((u0.w + u1.w) + (u2.w + u3.w)) + ((u4.w + u5.w) + (u6.w + u7.w)); \
        (A1).x += ((v0.x + v1.x) + (v2.x + v3.x)) + ((v4.x + v5.x) + (v6.x + v7.x)); \
        (A1).y += ((v0.y + v1.y) + (v2.y + v3.y)) + ((v4.y + v5.y) + (v6.y + v7.y)); \
        (A1).z += ((v0.z + v1.z) + (v2.z + v3.z)) + ((v4.z + v5.z) + (v6.z + v7.z)); \
        (A1).w += ((v0.w + v1.w) + (v2.w + v3.w)) + ((v4.w + v5.w) + (v6.w + v7.w)); \
    } while (0)

#define GATHER_TAIL(P0, P1, ROWP, I, A0, A1)                                  \
    do {                                                                      \
        unsigned r = (ROWP)[I];                                               \
        float4 u = (P0)[r], v = (P1)[r];                                      \
        (A0).x += u.x; (A0).y += u.y; (A0).z += u.z; (A0).w += u.w;           \
        (A1).x += v.x; (A1).y += v.y; (A1).z += v.z; (A1).w += v.w;           \
    } while (0)

// ---------------------------------------------------------------------------
// layer1: 2 CTAs/graph; p tile in smem; gather via LDS; conv1 MLP; q -> g_q
// ---------------------------------------------------------------------------
__global__ void __launch_bounds__(1024) layer1_kernel(
    const float* __restrict__ b1a, const float* __restrict__ W1b,
    const float* __restrict__ b1b, const float* __restrict__ W2a, int NN)
{
    extern __shared__ float4 smp[];
    float4* sP0 = smp;
    float4* sP1 = smp + NN_TILE;
    __shared__ float sb1a[F], sb1b[F], sW1b[F * F], sW2a[F * F];

    const int tid = threadIdx.x;
    const int g = blockIdx.x >> 1;
    const int half = blockIdx.x & 1;

    if (tid < F) { sb1a[tid] = b1a[tid]; sb1b[tid] = b1b[tid]; }
    if (tid < F * F) { sW1b[tid] = W1b[tid]; sW2a[tid] = W2a[tid]; }

    const float4* src = (const float4*)(g_p + (size_t)g * NN * F);
    for (int i = tid; i < NN * 2; i += 1024) {
        float4 v = src[i];
        if (i & 1) sP1[i >> 1] = v; else sP0[i >> 1] = v;
    }
    __syncthreads();

    const int nh = (NN + 1) >> 1;
    const int local = half * nh + tid;
    if (tid >= nh || local >= NN) return;
    const int n = g * NN + local;

    float4 a0 = sP0[local], a1 = sP1[local];     // self term (eps = 0)
    int deg = g_cnt[n]; if (deg > CAP) deg = CAP;
    const unsigned short* row = g_csr16 + (size_t)n * CAP;

    int i = 0;
    for (; i + 8 <= deg; i += 8) GATHER8(sP0, sP1, row, i, a0, a1);
    for (; i < deg; i++) GATHER_TAIL(sP0, sP1, row, i, a0, a1);

    float z[F];
    z[0] = lrelu(a0.x + sb1a[0]); z[1] = lrelu(a0.y + sb1a[1]);
    z[2] = lrelu(a0.z + sb1a[2]); z[3] = lrelu(a0.w + sb1a[3]);
    z[4] = lrelu(a1.x + sb1a[4]); z[5] = lrelu(a1.y + sb1a[5]);
    z[6] = lrelu(a1.z + sb1a[6]); z[7] = lrelu(a1.w + sb1a[7]);

    float h[F];
#pragma unroll
    for (int o = 0; o < F; o++) {
        float a = sb1b[o];
#pragma unroll
        for (int k = 0; k < F; k++) a += z[k] * sW1b[k * F + o];
        h[o] = lrelu(a);                  // conv1 out + inter-layer lrelu
    }
    float q[F];
#pragma unroll
    for (int o = 0; o < F; o++) {
        float a = 0.f;
#pragma unroll
        for (int k = 0; k < F; k++) a += h[k] * sW2a[k * F + o];
        q[o] = a;
    }
    float4* qo = (float4*)(g_q + (size_t)n * F);
    qo[0] = make_float4(q[0], q[1], q[2], q[3]);
    qo[1] = make_float4(q[4], q[5], q[6], q[7]);
}

// ---------------------------------------------------------------------------
// layer2 + head + finalize: 2 CTAs/graph; q tile in smem; FC1/FC2; last CTA
// does bf2 + log_softmax and resets g_done. Also zeroes g_cnt (owner thread).
// ---------------------------------------------------------------------------
__global__ void __launch_bounds__(1024) layer2_kernel(
    const float* __restrict__ b2a, const float* __restrict__ W2b,
    const float* __restrict__ b2b, const float* __restrict__ Wf1,
    const float* __restrict__ bf1, const float* __restrict__ Wf2,
    const float* __restrict__ bf2, float* __restrict__ out, int NN, int B)
{
    extern __shared__ float4 smp[];
    float4* sP0 = smp;
    float4* sP1 = smp + NN_TILE;
    __shared__ float sb2a[F], sb2b[F], sW2b[F * F], sWf1[F];
    __shared__ float sred[64];
    __shared__ unsigned int s_t;

    const int tid = threadIdx.x;
    const int g = blockIdx.x >> 1;
    const int half = blockIdx.x & 1;

    if (tid < F) { sb2a[tid] = b2a[tid]; sb2b[tid] = b2b[tid]; sWf1[tid] = Wf1[tid]; }
    if (tid < F * F) sW2b[tid] = W2b[tid];

    const float4* src = (const float4*)(g_q + (size_t)g * NN * F);
    for (int i = tid; i < NN * 2; i += 1024) {
        float4 v = src[i];
        if (i & 1) sP1[i >> 1] = v; else sP0[i >> 1] = v;
    }
    __syncthreads();

    const int nh = (NN + 1) >> 1;
    const int local = half * nh + tid;
    const float bf1v = bf1[0];

    float c0 = 0.f, c1 = 0.f;
    if (tid < nh && local < NN) {
        const int n = g * NN + local;
        float4 a0 = sP0[local], a1 = sP1[local];
        int deg = g_cnt[n];
        g_cnt[n] = 0;                      // restore invariant for next replay
        if (deg > CAP) deg = CAP;
        const unsigned short* row = g_csr16 + (size_t)n * CAP;

        int i = 0;
        for (; i + 8 <= deg; i += 8) GATHER8(sP0, sP1, row, i, a0, a1);
        for (; i < deg; i++) GATHER_TAIL(sP0, sP1, row, i, a0, a1);

        float z[F];
        z[0] = lrelu(a0.x + sb2a[0]); z[1] = lrelu(a0.y + sb2a[1]);
        z[2] = lrelu(a0.z + sb2a[2]); z[3] = lrelu(a0.w + sb2a[3]);
        z[4] = lrelu(a1.x + sb2a[4]); z[5] = lrelu(a1.y + sb2a[5]);
        z[6] = lrelu(a1.z + sb2a[6]); z[7] = lrelu(a1.w + sb2a[7]);

        float fc1 = bf1v;
#pragma unroll
        for (int o = 0; o < F; o++) {
            float a = sb2b[o];
#pragma unroll
            for (int k = 0; k < F; k++) a += z[k] * sW2b[k * F + o];
            fc1 += lrelu(a) * sWf1[o];     // lrelu(h2) @ Wf1
        }
        float gv = lrelu(fc1);             // lrelu before FC2
        float2 wf = __ldg((const float2*)(Wf2 + (size_t)local * 2));
        c0 = gv * wf.x;
        c1 = gv * wf.y;
    }
#pragma unroll
    for (int off = 16; off > 0; off >>= 1) {
        c0 += __shfl_down_sync(0xffffffffu, c0, off);
        c1 += __shfl_down_sync(0xffffffffu, c1, off);
    }
    int wid = tid >> 5, lid = tid & 31;
    if (lid == 0) { sred[wid] = c0; sred[wid + 32] = c1; }
    __syncthreads();
    if (tid == 0) {
        float s0 = 0.f, s1 = 0.f;
        for (int w = 0; w < 32; w++) { s0 += sred[w]; s1 += sred[w + 32]; }
        g_y[g * 4 + half * 2 + 0] = s0;    // per-(graph,half): no atomics
        g_y[g * 4 + half * 2 + 1] = s1;
        __threadfence();                   // release g_y before done-count
        s_t = atomicAdd(&g_done, 1u);
    }
    __syncthreads();
    if (s_t == (unsigned int)(gridDim.x - 1)) {
        __threadfence();                   // acquire: all g_y stores visible
        if (tid < B) {
            float y0 = g_y[tid * 4 + 0] + g_y[tid * 4 + 2] + bf2[0];
            float y1 = g_y[tid * 4 + 1] + g_y[tid * 4 + 3] + bf2[1];
            float m = fmaxf(y0, y1);
            float l = logf(expf(y0 - m) + expf(y1 - m));
            out[tid * 2 + 0] = y0 - m - l;
            out[tid * 2 + 1] = y1 - m - l;
        }
        if (tid == 0) g_done = 0;          // reset for next replay
    }
}

// ---------------------------------------------------------------------------
extern "C" void kernel_launch(void* const* d_in, const int* in_sizes, int n_in,
                              void* d_out, int out_size) {
    const float* x   = (const float*)d_in[0];
    const void*  ei  = d_in[1];
    const float* W1a = (const float*)d_in[3];
    const float* b1a = (const float*)d_in[4];
    const float* W1b = (const float*)d_in[5];
    const float* b1b = (const float*)d_in[6];
    const float* W2a = (const float*)d_in[7];
    const float* b2a = (const float*)d_in[8];
    const float* W2b = (const float*)d_in[9];
    const float* b2b = (const float*)d_in[10];
    const float* Wf1 = (const float*)d_in[11];
    const float* bf1 = (const float*)d_in[12];
    const float* Wf2 = (const float*)d_in[13];
    const float* bf2 = (const float*)d_in[14];
    float* out = (float*)d_out;

    int N = in_sizes[0] / NF;          // 128000
    int E = in_sizes[1] / 2;           // 2048000
    int B = out_size / 2;              // 64
    int NN = N / B;                    // 2000
    if (N > N_MAX) N = N_MAX;

    unsigned long long magic = ((1ull << 45) / (unsigned long long)NN) + 1ull;

    int projB = (N + 255) / 256;       // 500
    int scatB = (E + 1023) / 1024;     // 2000
    work_kernel<<<projB + scatB, 256>>>(x, W1a, ei, N, E, NN, magic, projB);

    size_t smem = (size_t)NN_TILE * 2 * sizeof(float4);   // 64 KB
    cudaFuncSetAttribute(layer1_kernel,
                         cudaFuncAttributeMaxDynamicSharedMemorySize, (int)smem);
    cudaFuncSetAttribute(layer2_kernel,
                         cudaFuncAttributeMaxDynamicSharedMemorySize, (int)smem);
    layer1_kernel<<<B * 2, 1024, smem>>>(b1a, W1b, b1b, W2a, NN);
    layer2_kernel<<<B * 2, 1024, smem>>>(b2a, W2b, b2b, Wf1, bf1, Wf2,
                                         bf2, out, NN, B);
}

// round 13
// speedup vs baseline: 1.7970x; 1.0234x over previous
#include <cuda_runtime.h>
#include <math.h>

#define NF 128
#define F 8
#define CAP 64            // padded CSR slots per node (deg ~ Poisson(16))
#define N_MAX 131072
#define B_MAX 64
#define NN_TILE 2048

// scratch (module-static, allowed; BSS zero-initialized at load)
__device__ unsigned short g_csr16[(size_t)N_MAX * CAP];  // 16 MB, local src ids
__device__ int            g_cnt[N_MAX];                  // re-zeroed by layer2
__device__ float          g_p[(size_t)N_MAX * F];        // x @ W1a
__device__ float          g_q[(size_t)N_MAX * F];        // h @ W2a
__device__ float          g_y[B_MAX * 4];                // [graph][half][class]
__device__ unsigned int   g_done;                        // reset by last CTA

__device__ __forceinline__ float lrelu(float v) {
    return v >= 0.f ? v : 0.01f * v;
}

// ---------------------------------------------------------------------------
// Fused proj (smem-tiled x@W1a) + scatter (CSR build, 4 edges/thread).
// __launch_bounds__(256, 6): caps regs at 42 so the proj branch cannot tax
// the latency-bound scatter blocks' occupancy (R10 lesson).
// Scatter blocks self-detect the edge dtype: int64 -> first 256 high 32-bit
// words are all zero (node ids < 2^31).
// magic = floor(2^45/NN)+1: grp = (d*magic)>>45 exact for d < 2^34.
// ---------------------------------------------------------------------------
__global__ void __launch_bounds__(256, 6) work_kernel(
    const float* __restrict__ x, const float* __restrict__ W1a,
    const void* __restrict__ ei, int N, int E, int NN,
    unsigned long long magic, int projB)
{
    if ((int)blockIdx.x < projB) {
        // ---------- proj: smem-tiled, 8 chunks of 16 k ----------
        __shared__ __align__(16) float sw[NF * F];   // [k][o], 4 KB
        __shared__ float sx[256 * 17];               // 256 nodes x 16 k, pad 1
        int tid = threadIdx.x;
        for (int i = tid; i < NF * F; i += 256) sw[i] = W1a[i];

        const int n0 = blockIdx.x * 256;
        float acc[F];
#pragma unroll
        for (int o = 0; o < F; o++) acc[o] = 0.f;

        for (int kc = 0; kc < 8; kc++) {
            __syncthreads();
            // staging: warp covers 2 rows x 64B -> 2 wavefronts/instr
#pragma unroll 4
            for (int it = 0; it < 16; it++) {
                int j = it * 256 + tid;
                int r = j >> 4, c = j & 15;
                int row = n0 + r; if (row >= N) row = N - 1;
                sx[r * 17 + c] = __ldg(&x[(size_t)row * NF + kc * 16 + c]);
            }
            __syncthreads();
            const float* myrow = &sx[tid * 17];  // stride 17: conflict-free
#pragma unroll
            for (int c = 0; c < 16; c++) {
                float xk = myrow[c];
                int k = kc * 16 + c;
                float4 w0 = *(const float4*)&sw[k * F];      // broadcast
                float4 w1 = *(const float4*)&sw[k * F + 4];  // broadcast
                acc[0] += xk * w0.x; acc[1] += xk * w0.y;
                acc[2] += xk * w0.z; acc[3] += xk * w0.w;
                acc[4] += xk * w1.x; acc[5] += xk * w1.y;
                acc[6] += xk * w1.z; acc[7] += xk * w1.w;
            }
        }
        int n = n0 + tid;
        if (n < N) {
            float4* o4 = (float4*)(g_p + (size_t)n * F);
            o4[0] = make_float4(acc[0], acc[1], acc[2], acc[3]);
            o4[1] = make_float4(acc[4], acc[5], acc[6], acc[7]);
        }
    } else {
        // ---------- scatter: 4 edges/thread, wide loads, magic div ----------
        __shared__ unsigned int sdet[8];
        int tid = threadIdx.x;
        unsigned int v = ((const unsigned int*)ei)[2 * tid + 1];  // E >= 256
#pragma unroll
        for (int off = 16; off > 0; off >>= 1)
            v |= __shfl_xor_sync(0xffffffffu, v, off);
        if ((tid & 31) == 0) sdet[tid >> 5] = v;
        __syncthreads();
        unsigned int all = sdet[0] | sdet[1] | sdet[2] | sdet[3]
                         | sdet[4] | sdet[5] | sdet[6] | sdet[7];
        int is64 = (all == 0u);

        int e0 = (blockIdx.x - projB) * 1024 + tid * 4;
        if (e0 >= E) return;

        unsigned int s[4], d[4];
        int cnt4 = (E - e0 >= 4) ? 4 : (E - e0);
        if (is64) {
            const long long* p = (const long long*)ei;
            if (cnt4 == 4) {
                ulonglong2 sa = *(const ulonglong2*)(p + e0);
                ulonglong2 sb = *(const ulonglong2*)(p + e0 + 2);
                ulonglong2 da = *(const ulonglong2*)(p + (size_t)E + e0);
                ulonglong2 db = *(const ulonglong2*)(p + (size_t)E + e0 + 2);
                s[0] = (unsigned int)sa.x; s[1] = (unsigned int)sa.y;
                s[2] = (unsigned int)sb.x; s[3] = (unsigned int)sb.y;
                d[0] = (unsigned int)da.x; d[1] = (unsigned int)da.y;
                d[2] = (unsigned int)db.x; d[3] = (unsigned int)db.y;
            } else {
                for (int j = 0; j < cnt4; j++) {
                    s[j] = (unsigned int)p[e0 + j];
                    d[j] = (unsigned int)p[(size_t)E + e0 + j];
                }
            }
        } else {
            const int* p = (const int*)ei;
            if (cnt4 == 4) {
                uint4 sa = *(const uint4*)(p + e0);
                uint4 da = *(const uint4*)(p + (size_t)E + e0);
                s[0] = sa.x; s[1] = sa.y; s[2] = sa.z; s[3] = sa.w;
                d[0] = da.x; d[1] = da.y; d[2] = da.z; d[3] = da.w;
            } else {
                for (int j = 0; j < cnt4; j++) {
                    s[j] = (unsigned int)p[e0 + j];
                    d[j] = (unsigned int)p[(size_t)E + e0 + j];
                }
            }
        }
        // issue all atomics back-to-back (independent -> 4 in flight)
        int pos[4];
#pragma unroll
        for (int j = 0; j < 4; j++)
            if (j < cnt4) pos[j] = atomicAdd(&g_cnt[d[j]], 1);
#pragma unroll
        for (int j = 0; j < 4; j++) {
            if (j < cnt4) {
                unsigned int grp =
                    (unsigned int)(((unsigned long long)d[j] * magic) >> 45);
                unsigned int base = grp * (unsigned int)NN;
                int p4 = pos[j]; if (p4 > CAP - 1) p4 = CAP - 1;
                g_csr16[(size_t)d[j] * CAP + p4] =
                    (unsigned short)(s[j] - base);
            }
        }
    }
}

// ---------------------------------------------------------------------------
// Shared-memory gather: acc += plane[idx] for 8 packed ushort ids
// ---------------------------------------------------------------------------
#define GATHER8(P0, P1, ROWP, I, A0, A1)                                      \
    do {                                                                      \
        uint4 w = *(const uint4*)((ROWP) + (I));                              \
        unsigned r0 = w.x & 0xffffu, r1 = w.x >> 16;                          \
        unsigned r2 = w.y & 0xffffu, r3 = w.y >> 16;                          \
        unsigned r4 = w.z & 0xffffu, r5 = w.z >> 16;                          \
        unsigned r6 = w.w & 0xffffu, r7 = w.w >> 16;                          \
        float4 u0 = (P0)[r0], u1 = (P0)[r1], u2 = (P0)[r2], u3 = (P0)[r3];    \
        float4 u4 = (P0)[r4], u5 = (P0)[r5], u6 = (P0)[r6], u7 = (P0)[r7];    \
        float4 v0 = (P1)[r0], v1 = (P1)[r1], v2 = (P1)[r2], v3 = (P1)[r3];    \
        float4 v4 = (P1)[r4], v5 = (P1)[r5], v6 = (P1)[r6], v7 = (P1)[r7];    \
        (A0).x += ((u0.x + u1.x) + (u2.x + u3.x)) + ((u4.x + u5.x) + (u6.x + u7.x)); \
        (A0).y += ((u0.y + u1.y) + (u2.y + u3.y)) + ((u4.y + u5.y) + (u6.y + u7.y)); \
        (A0).z += ((u0.z + u1.z) + (u2.z + u3.z)) + ((u4.z + u5.z) + (u6.z + u7.z)); \
        (A0).w += ((u0.w + u1.w) + (u2.w + u3.w)) + ((u4.w + u5.w) + (u6.w + u7.w)); \
        (A1).x += ((v0.x + v1.x) + (v2.x + v3.x)) + ((v4.x + v5.x) + (v6.x + v7.x)); \
        (A1).y += ((v0.y + v1.y) + (v2.y + v3.y)) + ((v4.y + v5.y) + (v6.y + v7.y)); \
        (A1).z += ((v0.z + v1.z) + (v2.z + v3.z)) + ((v4.z + v5.z) + (v6.z + v7.z)); \
        (A1).w += ((v0.w + v1.w) + (v2.w + v3.w)) + ((v4.w + v5.w) + (v6.w + v7.w)); \
    } while (0)

#define GATHER_TAIL(P0, P1, ROWP, I, A0, A1)                                  \
    do {                                                                      \
        unsigned r = (ROWP)[I];                                               \
        float4 u = (P0)[r], v = (P1)[r];                                      \
        (A0).x += u.x; (A0).y += u.y; (A0).z += u.z; (A0).w += u.w;           \
        (A1).x += v.x; (A1).y += v.y; (A1).z += v.z; (A1).w += v.w;           \
    } while (0)

// ---------------------------------------------------------------------------
// layer1: 2 CTAs/graph; p tile in smem; gather via LDS; conv1 MLP; q -> g_q
// ---------------------------------------------------------------------------
__global__ void __launch_bounds__(1024) layer1_kernel(
    const float* __restrict__ b1a, const float* __restrict__ W1b,
    const float* __restrict__ b1b, const float* __restrict__ W2a, int NN)
{
    extern __shared__ float4 smp[];
    float4* sP0 = smp;
    float4* sP1 = smp + NN_TILE;
    __shared__ float sb1a[F], sb1b[F], sW1b[F * F], sW2a[F * F];

    const int tid = threadIdx.x;
    const int g = blockIdx.x >> 1;
    const int half = blockIdx.x & 1;

    if (tid < F) { sb1a[tid] = b1a[tid]; sb1b[tid] = b1b[tid]; }
    if (tid < F * F) { sW1b[tid] = W1b[tid]; sW2a[tid] = W2a[tid]; }

    const float4* src = (const float4*)(g_p + (size_t)g * NN * F);
    for (int i = tid; i < NN * 2; i += 1024) {
        float4 v = src[i];
        if (i & 1) sP1[i >> 1] = v; else sP0[i >> 1] = v;
    }
    __syncthreads();

    const int nh = (NN + 1) >> 1;
    const int local = half * nh + tid;
    if (tid >= nh || local >= NN) return;
    const int n = g * NN + local;

    float4 a0 = sP0[local], a1 = sP1[local];     // self term (eps = 0)
    int deg = g_cnt[n]; if (deg > CAP) deg = CAP;
    const unsigned short* row = g_csr16 + (size_t)n * CAP;

    int i = 0;
    for (; i + 8 <= deg; i += 8) GATHER8(sP0, sP1, row, i, a0, a1);
    for (; i < deg; i++) GATHER_TAIL(sP0, sP1, row, i, a0, a1);

    float z[F];
    z[0] = lrelu(a0.x + sb1a[0]); z[1] = lrelu(a0.y + sb1a[1]);
    z[2] = lrelu(a0.z + sb1a[2]); z[3] = lrelu(a0.w + sb1a[3]);
    z[4] = lrelu(a1.x + sb1a[4]); z[5] = lrelu(a1.y + sb1a[5]);
    z[6] = lrelu(a1.z + sb1a[6]); z[7] = lrelu(a1.w + sb1a[7]);

    float h[F];
#pragma unroll
    for (int o = 0; o < F; o++) {
        float a = sb1b[o];
#pragma unroll
        for (int k = 0; k < F; k++) a += z[k] * sW1b[k * F + o];
        h[o] = lrelu(a);                  // conv1 out + inter-layer lrelu
    }
    float q[F];
#pragma unroll
    for (int o = 0; o < F; o++) {
        float a = 0.f;
#pragma unroll
        for (int k = 0; k < F; k++) a += h[k] * sW2a[k * F + o];
        q[o] = a;
    }
    float4* qo = (float4*)(g_q + (size_t)n * F);
    qo[0] = make_float4(q[0], q[1], q[2], q[3]);
    qo[1] = make_float4(q[4], q[5], q[6], q[7]);
}

// ---------------------------------------------------------------------------
// layer2 + head + finalize: 2 CTAs/graph; q tile in smem; FC1/FC2; last CTA
// does bf2 + log_softmax and resets g_done. Also zeroes g_cnt (owner thread).
// ---------------------------------------------------------------------------
__global__ void __launch_bounds__(1024) layer2_kernel(
    const float* __restrict__ b2a, const float* __restrict__ W2b,
    const float* __restrict__ b2b, const float* __restrict__ Wf1,
    const float* __restrict__ bf1, const float* __restrict__ Wf2,
    const float* __restrict__ bf2, float* __restrict__ out, int NN, int B)
{
    extern __shared__ float4 smp[];
    float4* sP0 = smp;
    float4* sP1 = smp + NN_TILE;
    __shared__ float sb2a[F], sb2b[F], sW2b[F * F], sWf1[F];
    __shared__ float sred[64];
    __shared__ unsigned int s_t;

    const int tid = threadIdx.x;
    const int g = blockIdx.x >> 1;
    const int half = blockIdx.x & 1;

    if (tid < F) { sb2a[tid] = b2a[tid]; sb2b[tid] = b2b[tid]; sWf1[tid] = Wf1[tid]; }
    if (tid < F * F) sW2b[tid] = W2b[tid];

    const float4* src = (const float4*)(g_q + (size_t)g * NN * F);
    for (int i = tid; i < NN * 2; i += 1024) {
        float4 v = src[i];
        if (i & 1) sP1[i >> 1] = v; else sP0[i >> 1] = v;
    }
    __syncthreads();

    const int nh = (NN + 1) >> 1;
    const int local = half * nh + tid;
    const float bf1v = bf1[0];

    float c0 = 0.f, c1 = 0.f;
    if (tid < nh && local < NN) {
        const int n = g * NN + local;
        float4 a0 = sP0[local], a1 = sP1[local];
        int deg = g_cnt[n];
        g_cnt[n] = 0;                      // restore invariant for next replay
        if (deg > CAP) deg = CAP;
        const unsigned short* row = g_csr16 + (size_t)n * CAP;

        int i = 0;
        for (; i + 8 <= deg; i += 8) GATHER8(sP0, sP1, row, i, a0, a1);
        for (; i < deg; i++) GATHER_TAIL(sP0, sP1, row, i, a0, a1);

        float z[F];
        z[0] = lrelu(a0.x + sb2a[0]); z[1] = lrelu(a0.y + sb2a[1]);
        z[2] = lrelu(a0.z + sb2a[2]); z[3] = lrelu(a0.w + sb2a[3]);
        z[4] = lrelu(a1.x + sb2a[4]); z[5] = lrelu(a1.y + sb2a[5]);
        z[6] = lrelu(a1.z + sb2a[6]); z[7] = lrelu(a1.w + sb2a[7]);

        float fc1 = bf1v;
#pragma unroll
        for (int o = 0; o < F; o++) {
            float a = sb2b[o];
#pragma unroll
            for (int k = 0; k < F; k++) a += z[k] * sW2b[k * F + o];
            fc1 += lrelu(a) * sWf1[o];     // lrelu(h2) @ Wf1
        }
        float gv = lrelu(fc1);             // lrelu before FC2
        float2 wf = __ldg((const float2*)(Wf2 + (size_t)local * 2));
        c0 = gv * wf.x;
        c1 = gv * wf.y;
    }
#pragma unroll
    for (int off = 16; off > 0; off >>= 1) {
        c0 += __shfl_down_sync(0xffffffffu, c0, off);
        c1 += __shfl_down_sync(0xffffffffu, c1, off);
    }
    int wid = tid >> 5, lid = tid & 31;
    if (lid == 0) { sred[wid] = c0; sred[wid + 32] = c1; }
    __syncthreads();
    if (tid == 0) {
        float s0 = 0.f, s1 = 0.f;
        for (int w = 0; w < 32; w++) { s0 += sred[w]; s1 += sred[w + 32]; }
        g_y[g * 4 + half * 2 + 0] = s0;    // per-(graph,half): no atomics
        g_y[g * 4 + half * 2 + 1] = s1;
        __threadfence();                   // release g_y before done-count
        s_t = atomicAdd(&g_done, 1u);
    }
    __syncthreads();
    if (s_t == (unsigned int)(gridDim.x - 1)) {
        __threadfence();                   // acquire: all g_y stores visible
        if (tid < B) {
            float y0 = g_y[tid * 4 + 0] + g_y[tid * 4 + 2] + bf2[0];
            float y1 = g_y[tid * 4 + 1] + g_y[tid * 4 + 3] + bf2[1];
            float m = fmaxf(y0, y1);
            float l = logf(expf(y0 - m) + expf(y1 - m));
            out[tid * 2 + 0] = y0 - m - l;
            out[tid * 2 + 1] = y1 - m - l;
        }
        if (tid == 0) g_done = 0;          // reset for next replay
    }
}

// ---------------------------------------------------------------------------
extern "C" void kernel_launch(void* const* d_in, const int* in_sizes, int n_in,
                              void* d_out, int out_size) {
    const float* x   = (const float*)d_in[0];
    const void*  ei  = d_in[1];
    const float* W1a = (const float*)d_in[3];
    const float* b1a = (const float*)d_in[4];
    const float* W1b = (const float*)d_in[5];
    const float* b1b = (const float*)d_in[6];
    const float* W2a = (const float*)d_in[7];
    const float* b2a = (const float*)d_in[8];
    const float* W2b = (const float*)d_in[9];
    const float* b2b = (const float*)d_in[10];
    const float* Wf1 = (const float*)d_in[11];
    const float* bf1 = (const float*)d_in[12];
    const float* Wf2 = (const float*)d_in[13];
    const float* bf2 = (const float*)d_in[14];
    float* out = (float*)d_out;

    int N = in_sizes[0] / NF;          // 128000
    int E = in_sizes[1] / 2;           // 2048000
    int B = out_size / 2;              // 64
    int NN = N / B;                    // 2000
    if (N > N_MAX) N = N_MAX;

    unsigned long long magic = ((1ull << 45) / (unsigned long long)NN) + 1ull;

    int projB = (N + 255) / 256;       // 500
    int scatB = (E + 1023) / 1024;     // 2000
    work_kernel<<<projB + scatB, 256>>>(x, W1a, ei, N, E, NN, magic, projB);

    size_t smem = (size_t)NN_TILE * 2 * sizeof(float4);   // 64 KB
    cudaFuncSetAttribute(layer1_kernel,
                         cudaFuncAttributeMaxDynamicSharedMemorySize, (int)smem);
    cudaFuncSetAttribute(layer2_kernel,
                         cudaFuncAttributeMaxDynamicSharedMemorySize, (int)smem);
    layer1_kernel<<<B * 2, 1024, smem>>>(b1a, W1b, b1b, W2a, NN);
    layer2_kernel<<<B * 2, 1024, smem>>>(b2a, W2b, b2b, Wf1, bf1, Wf2,
                                         bf2, out, NN, B);
}